// round 4
// baseline (speedup 1.0000x reference)
#include <cuda_runtime.h>
#include <cstdint>

// SpikeFP64ScaleBy2K — soft-logic FP64 scale-by-2^k collapsed to integer bit ops.
// R3: float4 per lane, HALF-WARP per row. One LDG.128 per lane serves two rows
// per warp issue -> ~2x fewer issues per byte vs R2. REDUX.ADD with per-half
// member masks; same verified packed-weight decode + scalar chain (rel_err 0).
//
// Row = 64 floats (0.0/1.0), MSB-first IEEE-754 double bit pattern.
// Half-lane l (0..15) holds bit positions p = 4l..4l+3.
//
// Packed reduction words (per half-warp = per row):
//   r1 = sum((e_k_weight << 16) | val_weight) over k bits
//        -> e_k = r1>>16 (<=0x7FF), val_frac = r1&0x7FFF
//   r2 = sum(e_x_weight | nz<<12 | sign<<20)
//        -> e_x = r2&0x7FF, nz-count bits 12..18, s_k bit 20

static constexpr int PAIRS_PER_WARP = 2;   // iterations; each covers 2 rows
static constexpr int WARPS_PER_BLOCK = 8;
static constexpr int BLOCK_THREADS = WARPS_PER_BLOCK * 32;
// rows per warp = 2 * PAIRS_PER_WARP = 4  (grid unchanged vs R2)

__global__ void __launch_bounds__(BLOCK_THREADS)
scale2k_kernel(const float4* __restrict__ x4,
               const float4* __restrict__ k4,
               float4* __restrict__ o4,
               int nrows)
{
    const int lane = threadIdx.x & 31;
    const int hl = lane & 15;                       // half-lane
    const unsigned rmask = (lane & 16) ? 0xFFFF0000u : 0x0000FFFFu;

    const int warp = blockIdx.x * WARPS_PER_BLOCK + (threadIdx.x >> 5);
    const int row0 = warp * (2 * PAIRS_PER_WARP);
    if (row0 >= nrows) return;                      // warp-uniform exit

    // ---- per-lane weights for bit positions p = 4*hl + c ----
    unsigned wE[4], w1[4], w2k[4], shp[4];
    bool isExp[4];
#pragma unroll
    for (int c = 0; c < 4; ++c) {
        const int p = 4 * hl + c;
        wE[c] = (p >= 1 && p <= 11) ? (1u << (11 - p)) : 0u;           // exponent weight
        const unsigned wV = (p >= 12 && p <= 26) ? (1u << (26 - p)) : 0u; // top-15 mantissa
        w1[c]  = (wE[c] << 16) | wV;
        w2k[c] = (p == 0) ? (1u << 20) : (1u << 12);                   // sign vs nz-count
        isExp[c] = (p >= 1 && p <= 11);
        shp[c] = isExp[c] ? (unsigned)(11 - p) : 0u;
    }
    const bool patch_lane = (hl <= 2);              // exponent bits live in hl 0..2

    // ---- front-batch loads: 4 independent LDG.128 per lane (MLP) ----
    // Row pair (row0+2r, row0+2r+1): 32 float4 slots; lane -> slot directly.
    float4 xv[PAIRS_PER_WARP], kv[PAIRS_PER_WARP];
#pragma unroll
    for (int r = 0; r < PAIRS_PER_WARP; ++r) {
        if (row0 + 2 * r < nrows) {                 // warp-uniform
            const long idx = (long)(row0 + 2 * r) * 16 + lane;
            xv[r] = __ldg(&x4[idx]);
            kv[r] = __ldg(&k4[idx]);
        }
    }

#pragma unroll
    for (int r = 0; r < PAIRS_PER_WARP; ++r) {
        if (row0 + 2 * r >= nrows) break;           // warp-uniform

        const float kx0 = kv[r].x, kx1 = kv[r].y, kx2 = kv[r].z, kx3 = kv[r].w;
        const float xx0 = xv[r].x, xx1 = xv[r].y, xx2 = xv[r].z, xx3 = xv[r].w;

        unsigned c1 = 0u, c2 = 0u;
        c1 += (kx0 != 0.0f) ? w1[0] : 0u;  c2 += (kx0 != 0.0f) ? w2k[0] : 0u;
        c1 += (kx1 != 0.0f) ? w1[1] : 0u;  c2 += (kx1 != 0.0f) ? w2k[1] : 0u;
        c1 += (kx2 != 0.0f) ? w1[2] : 0u;  c2 += (kx2 != 0.0f) ? w2k[2] : 0u;
        c1 += (kx3 != 0.0f) ? w1[3] : 0u;  c2 += (kx3 != 0.0f) ? w2k[3] : 0u;
        c2 += (xx0 != 0.0f) ? wE[0] : 0u;
        c2 += (xx1 != 0.0f) ? wE[1] : 0u;
        c2 += (xx2 != 0.0f) ? wE[2] : 0u;
        c2 += (xx3 != 0.0f) ? wE[3] : 0u;

        // Per-half reduction: each 16-lane group reduces its own row.
        const unsigned r1 = __reduce_add_sync(rmask, c1);
        const unsigned r2 = __reduce_add_sync(rmask, c2);

        // ---- scalar chain (verified bit-exact in R1/R2), per half ----
        const unsigned e_k   = r1 >> 16;
        const unsigned val   = 0x8000u | (r1 & 0xFFFFu);
        const unsigned t     = (~(e_k + 1025u)) & 15u;
        const unsigned k_abs = (val >> t) & 0x7FFu;
        const unsigned s_k   = (r2 >> 20) & 1u;
        const unsigned k_fin = s_k ? ((0u - k_abs) & 0x7FFu) : k_abs;
        const unsigned e_x   = r2 & 0x7FFu;
        const unsigned e_new = (e_x + k_fin) & 0x7FFu;
        const bool nz        = ((r2 >> 12) & 0xFFu) != 0u;

        // ---- patch exponent field (positions 1..11 -> hl 0..2) ----
        float4 ov = xv[r];
        if (nz && patch_lane) {
            if (isExp[0]) ov.x = (float)((e_new >> shp[0]) & 1u);
            if (isExp[1]) ov.y = (float)((e_new >> shp[1]) & 1u);
            if (isExp[2]) ov.z = (float)((e_new >> shp[2]) & 1u);
            if (isExp[3]) ov.w = (float)((e_new >> shp[3]) & 1u);
        }

        const long idx = (long)(row0 + 2 * r) * 16 + lane;
        o4[idx] = ov;
    }
}

extern "C" void kernel_launch(void* const* d_in, const int* in_sizes, int n_in,
                              void* d_out, int out_size) {
    const float4* x4 = (const float4*)d_in[0];
    const float4* k4 = (const float4*)d_in[1];
    float4* o4 = (float4*)d_out;

    const int nrows = in_sizes[0] / 64;
    const int rows_per_warp = 2 * PAIRS_PER_WARP;
    const int nwarps = (nrows + rows_per_warp - 1) / rows_per_warp;
    const int nblocks = (nwarps + WARPS_PER_BLOCK - 1) / WARPS_PER_BLOCK;

    scale2k_kernel<<<nblocks, BLOCK_THREADS>>>(x4, k4, o4, nrows);
}

// round 5
// speedup vs baseline: 1.0160x; 1.0160x over previous
#include <cuda_runtime.h>
#include <cstdint>

// SpikeFP64ScaleBy2K — soft-logic FP64 scale-by-2^k collapsed to integer bit ops.
// R4: R2 structure (float2/lane, warp-per-row, best @115.9us) with the ALU-pipe
// decode moved off the critical pipe:
//   - bit extract = (bits>>29) single SHF (inputs are exactly 0.0f/1.0f)
//   - weight accumulation via b*w IMADs (fma pipe, 10.8% utilized)
//   - exponent patch via IMAD * 0x3F800000 (no I2F), predicated (no branch)
// Field packing + scalar chain identical to R2 (verified rel_err 0).

static constexpr int ROWS_PER_WARP = 4;
static constexpr int WARPS_PER_BLOCK = 8;
static constexpr int BLOCK_THREADS = WARPS_PER_BLOCK * 32;

__global__ void __launch_bounds__(BLOCK_THREADS)
scale2k_kernel(const uint2* __restrict__ x2,
               const uint2* __restrict__ k2,
               uint2* __restrict__ o2,
               int nrows)
{
    const int lane = threadIdx.x & 31;
    const int warp = blockIdx.x * WARPS_PER_BLOCK + (threadIdx.x >> 5);
    const int row0 = warp * ROWS_PER_WARP;
    if (row0 >= nrows) return;  // warp-uniform exit

    // ---- per-lane weights (hoisted; lane j holds bit positions 2j, 2j+1) ----
    // exponent weights: position p in 1..11 -> 2^(11-p)
    const unsigned wE_x = (lane >= 1 && lane <= 5) ? (1u << (11 - 2 * lane)) : 0u;
    const unsigned wE_y = (lane <= 5) ? (1u << (10 - 2 * lane)) : 0u;
    // top-15 mantissa weights: position p in 12..26 -> 2^(26-p)
    const unsigned wV_x = (lane >= 6 && lane <= 13) ? (1u << (26 - 2 * lane)) : 0u;
    const unsigned wV_y = (lane >= 6 && lane <= 12) ? (1u << (25 - 2 * lane)) : 0u;
    const unsigned w1x = (wE_x << 16) | wV_x;
    const unsigned w1y = (wE_y << 16) | wV_y;
    // flags: k[0] -> sign (bit 20); every other k bit -> nz-count (bit 12)
    const unsigned w2kx = (lane == 0) ? (1u << 20) : (1u << 12);
    const unsigned w2ky = 1u << 12;
    // patch shifts for lanes 0..5
    const unsigned sh_x = (unsigned)(11 - 2 * lane) & 31u;
    const unsigned sh_y = (unsigned)(10 - 2 * lane) & 31u;
    const bool lane_le5 = (lane <= 5);
    const bool lane_ge1 = (lane >= 1);

    // ---- front-batch loads: 8 independent LDG.64 per lane (MLP) ----
    uint2 xv[ROWS_PER_WARP];
    uint2 kv[ROWS_PER_WARP];
#pragma unroll
    for (int r = 0; r < ROWS_PER_WARP; ++r) {
        if (row0 + r < nrows) {  // warp-uniform
            const long idx = (long)(row0 + r) * 32 + lane;
            xv[r] = __ldg(&x2[idx]);
            kv[r] = __ldg(&k2[idx]);
        }
    }

#pragma unroll
    for (int r = 0; r < ROWS_PER_WARP; ++r) {
        if (row0 + r >= nrows) break;  // warp-uniform

        // Inputs are exactly 0.0f (0x00000000) or 1.0f (0x3F800000): bit = u>>29.
        const unsigned bkx = kv[r].x >> 29;
        const unsigned bky = kv[r].y >> 29;
        const unsigned bxx = xv[r].x >> 29;
        const unsigned bxy = xv[r].y >> 29;

        // Weight accumulation as IMADs (fma pipe).
        const unsigned c1 = bkx * w1x + bky * w1y;
        const unsigned c2 = bxx * wE_x + bxy * wE_y + bkx * w2kx + bky * w2ky;

        const unsigned r1 = __reduce_add_sync(0xFFFFFFFFu, c1);
        const unsigned r2 = __reduce_add_sync(0xFFFFFFFFu, c2);

        // ---- uniform scalar chain (verified bit-exact R1/R2) ----
        const unsigned e_k   = r1 >> 16;
        const unsigned val   = 0x8000u | (r1 & 0xFFFFu);
        const unsigned t     = (~(e_k + 1025u)) & 15u;
        const unsigned k_abs = (val >> t) & 0x7FFu;
        const unsigned s_k   = (r2 >> 20) & 1u;
        const unsigned k_fin = s_k ? ((0u - k_abs) & 0x7FFu) : k_abs;
        const unsigned e_x   = r2 & 0x7FFu;
        const unsigned e_new = (e_x + k_fin) & 0x7FFu;
        const bool nz        = ((r2 >> 12) & 0xFFu) != 0u;

        // ---- patch exponent field (bits 1..11 -> lanes 0..5), branch-free ----
        // bit -> float via *0x3F800000 (IMAD), selected by predicate.
        const unsigned px = ((e_new >> sh_x) & 1u) * 0x3F800000u;
        const unsigned py = ((e_new >> sh_y) & 1u) * 0x3F800000u;

        uint2 ov = xv[r];
        const bool patch = nz && lane_le5;
        ov.x = (patch && lane_ge1) ? px : ov.x;
        ov.y = patch ? py : ov.y;

        const long idx = (long)(row0 + r) * 32 + lane;
        o2[idx] = ov;
    }
}

extern "C" void kernel_launch(void* const* d_in, const int* in_sizes, int n_in,
                              void* d_out, int out_size) {
    const uint2* x2 = (const uint2*)d_in[0];
    const uint2* k2 = (const uint2*)d_in[1];
    uint2* o2 = (uint2*)d_out;

    const int nrows = in_sizes[0] / 64;
    const int nwarps = (nrows + ROWS_PER_WARP - 1) / ROWS_PER_WARP;
    const int nblocks = (nwarps + WARPS_PER_BLOCK - 1) / WARPS_PER_BLOCK;

    scale2k_kernel<<<nblocks, BLOCK_THREADS>>>(x2, k2, o2, nrows);
}